// round 1
// baseline (speedup 1.0000x reference)
#include <cuda_runtime.h>
#include <cuda_bf16.h>

#define MAXN 100000
#define MAXE 1600000
#define MAXF 128

// ---------------- scratch (device globals; no cudaMalloc allowed) ----------------
__device__ float g_bufA[MAXN * MAXF];
__device__ float g_bufB[MAXN * MAXF];
__device__ int   g_deg[MAXN];
__device__ float g_dinv[MAXN];
__device__ int   g_rowptr[MAXN + 1];
__device__ int   g_fill[MAXN];
__device__ int   g_esrc[MAXE];
__device__ float g_enrm[MAXE];

// ---------------- preprocessing kernels ----------------
__global__ void zero_kernel(int N) {
    int i = blockIdx.x * blockDim.x + threadIdx.x;
    if (i < N) { g_deg[i] = 0; g_fill[i] = 0; }
}

__global__ void deg_kernel(const int* __restrict__ dst, int E) {
    int e = blockIdx.x * blockDim.x + threadIdx.x;
    if (e < E) atomicAdd(&g_deg[dst[e]], 1);
}

__global__ void dinv_kernel(int N) {
    int i = blockIdx.x * blockDim.x + threadIdx.x;
    if (i < N) g_dinv[i] = rsqrtf((float)g_deg[i] + 1.0f);
}

// single-block exclusive scan of g_deg -> g_rowptr (N ~ 100k)
__global__ void scan_kernel(int N) {
    const int T = 1024;
    int t = threadIdx.x;
    int chunk = (N + T - 1) / T;
    int beg = t * chunk;
    int end = beg + chunk; if (end > N) end = N;
    int s = 0;
    for (int i = beg; i < end; i++) s += g_deg[i];
    __shared__ int sh[T];
    sh[t] = s;
    __syncthreads();
    for (int o = 1; o < T; o <<= 1) {
        int v = (t >= o) ? sh[t - o] : 0;
        __syncthreads();
        sh[t] += v;
        __syncthreads();
    }
    int run = (t == 0) ? 0 : sh[t - 1];
    for (int i = beg; i < end; i++) { g_rowptr[i] = run; run += g_deg[i]; }
    if (t == T - 1) g_rowptr[N] = sh[T - 1];
}

__global__ void scatter_kernel(const int* __restrict__ src, const int* __restrict__ dst, int E) {
    int e = blockIdx.x * blockDim.x + threadIdx.x;
    if (e >= E) return;
    int s = src[e], d = dst[e];
    int pos = g_rowptr[d] + atomicAdd(&g_fill[d], 1);
    g_esrc[pos] = s;
    g_enrm[pos] = g_dinv[s] * g_dinv[d];
}

// ---------------- GEMM: out[n][f] = sum_k in[n][k]*W[k][f] (+b, relu opt) ----------------
// 128 threads/block; GROUPS = 128/F thread-groups; each group handles NPG nodes.
template <int K, int F, int NPG, bool BIAS, bool RELU>
__global__ void gemm_kernel(const float* __restrict__ in, const float* __restrict__ W,
                            const float* __restrict__ b, float* __restrict__ out, int N) {
    constexpr int GROUPS = 128 / F;
    constexpr int NT = NPG * GROUPS;
    __shared__ float sx[NT * K];
    int base = blockIdx.x * NT;
    for (int i = threadIdx.x; i < NT * K; i += 128) {
        int r = i / K, c = i % K;
        int n = base + r;
        sx[i] = (n < N) ? in[n * K + c] : 0.0f;
    }
    __syncthreads();
    int f = threadIdx.x % F;
    int g = threadIdx.x / F;
    float acc[NPG];
#pragma unroll
    for (int j = 0; j < NPG; j++) acc[j] = 0.0f;

    if constexpr (K % 4 == 0) {
        for (int k = 0; k < K; k += 4) {
            float w0 = W[(k + 0) * F + f];
            float w1 = W[(k + 1) * F + f];
            float w2 = W[(k + 2) * F + f];
            float w3 = W[(k + 3) * F + f];
#pragma unroll
            for (int j = 0; j < NPG; j++) {
                const float4 x4 = *reinterpret_cast<const float4*>(&sx[(g * NPG + j) * K + k]);
                acc[j] = fmaf(x4.x, w0, acc[j]);
                acc[j] = fmaf(x4.y, w1, acc[j]);
                acc[j] = fmaf(x4.z, w2, acc[j]);
                acc[j] = fmaf(x4.w, w3, acc[j]);
            }
        }
    } else {
        for (int k = 0; k < K; k++) {
            float wv = W[k * F + f];
#pragma unroll
            for (int j = 0; j < NPG; j++)
                acc[j] = fmaf(sx[(g * NPG + j) * K + k], wv, acc[j]);
        }
    }
    float bv = BIAS ? b[f] : 0.0f;
#pragma unroll
    for (int j = 0; j < NPG; j++) {
        int n = base + g * NPG + j;
        if (n < N) {
            float v = acc[j] + bv;
            if (RELU) v = fmaxf(v, 0.0f);
            out[n * F + f] = v;
        }
    }
}

// ---------------- Aggregation: out = A*h (+b, relu opt) via CSR ----------------
template <int F, bool BIAS, bool RELU>
__global__ void agg_kernel(const float* __restrict__ h, float* __restrict__ out,
                           const float* __restrict__ b, int N) {
    constexpr int NPB = 128 / F;
    int n = blockIdx.x * NPB + threadIdx.x / F;
    if (n >= N) return;
    int f = threadIdx.x % F;
    float di = g_dinv[n];
    float acc = h[n * F + f] * di * di;
    int beg = g_rowptr[n], end = g_rowptr[n + 1];
    for (int j = beg; j < end; j++) {
        int s = g_esrc[j];
        float nm = g_enrm[j];
        acc = fmaf(h[s * F + f], nm, acc);
    }
    if (BIAS) acc += b[f];
    if (RELU) acc = fmaxf(acc, 0.0f);
    out[n * F + f] = acc;
}

// ---------------- final linear: out[n] = x[n,0:64] . Wl + bl ----------------
__global__ void linear_kernel(const float* __restrict__ x, const float* __restrict__ Wl,
                              const float* __restrict__ bl, float* __restrict__ out, int N) {
    int warp = (blockIdx.x * blockDim.x + threadIdx.x) >> 5;
    int lane = threadIdx.x & 31;
    if (warp >= N) return;
    float v = x[warp * 64 + lane] * Wl[lane] + x[warp * 64 + 32 + lane] * Wl[32 + lane];
#pragma unroll
    for (int o = 16; o; o >>= 1) v += __shfl_xor_sync(0xFFFFFFFFu, v, o);
    if (lane == 0) out[warp] = v + bl[0];
}

// ---------------- launch ----------------
extern "C" void kernel_launch(void* const* d_in, const int* in_sizes, int n_in,
                              void* d_out, int out_size) {
    const float* x  = (const float*)d_in[0];
    const int*   ei = (const int*)d_in[1];
    int wb = n_in - 12;  // weights start (batch_size scalar may or may not be an input)
    const float* W1 = (const float*)d_in[wb + 0];
    const float* b1 = (const float*)d_in[wb + 1];
    const float* W2 = (const float*)d_in[wb + 2];
    const float* b2 = (const float*)d_in[wb + 3];
    const float* W3 = (const float*)d_in[wb + 4];
    const float* b3 = (const float*)d_in[wb + 5];
    const float* W4 = (const float*)d_in[wb + 6];
    const float* b4 = (const float*)d_in[wb + 7];
    const float* W5 = (const float*)d_in[wb + 8];
    const float* b5 = (const float*)d_in[wb + 9];
    const float* Wl = (const float*)d_in[wb + 10];
    const float* bl = (const float*)d_in[wb + 11];
    float* out = (float*)d_out;

    int N = in_sizes[0] / 2;
    int E = in_sizes[1] / 2;
    const int* src = ei;
    const int* dst = ei + E;

    float *bufA, *bufB;
    cudaGetSymbolAddress((void**)&bufA, g_bufA);
    cudaGetSymbolAddress((void**)&bufB, g_bufB);

    // ---- build normalized CSR (dst-sorted edges) ----
    zero_kernel<<<(N + 255) / 256, 256>>>(N);
    deg_kernel<<<(E + 255) / 256, 256>>>(dst, E);
    dinv_kernel<<<(N + 255) / 256, 256>>>(N);
    scan_kernel<<<1, 1024>>>(N);
    scatter_kernel<<<(E + 255) / 256, 256>>>(src, dst, E);

    // ---- layer 1: t = A x (F=2) ; x1 = relu(t W1 + b1) ----
    agg_kernel<2, false, false><<<(N + 63) / 64, 128>>>(x, bufB, nullptr, N);
    gemm_kernel<2, 128, 8, true, true><<<(N + 7) / 8, 128>>>(bufB, W1, b1, bufA, N);

    // ---- layer 2: t = A x1 (F=128) ; x2 = relu(t W2 + b2) ----
    agg_kernel<128, false, false><<<N, 128>>>(bufA, bufB, nullptr, N);
    gemm_kernel<128, 128, 8, true, true><<<(N + 7) / 8, 128>>>(bufB, W2, b2, bufA, N);

    // ---- layer 3: t = x2 W3 (no bias) ; x3 = relu(A t + b3) (F=32) ----
    gemm_kernel<128, 32, 8, false, false><<<(N + 31) / 32, 128>>>(bufA, W3, nullptr, bufB, N);
    agg_kernel<32, true, true><<<(N + 3) / 4, 128>>>(bufB, bufA, b3, N);

    // ---- layer 4: t = A x3 (F=32) ; x4 = relu(t W4 + b4) ----
    agg_kernel<32, false, false><<<(N + 3) / 4, 128>>>(bufA, bufB, nullptr, N);
    gemm_kernel<32, 32, 8, true, true><<<(N + 31) / 32, 128>>>(bufB, W4, b4, bufA, N);

    // ---- layer 5: t = A x4 (F=32) ; x5 = relu(t W5 + b5) (F=64) ----
    agg_kernel<32, false, false><<<(N + 3) / 4, 128>>>(bufA, bufB, nullptr, N);
    gemm_kernel<32, 64, 8, true, true><<<(N + 15) / 16, 128>>>(bufB, W5, b5, bufA, N);

    // ---- final linear 64 -> 1 ----
    linear_kernel<<<(N * 32 + 255) / 256, 256>>>(bufA, Wl, bl, out, N);
}

// round 2
// speedup vs baseline: 1.3472x; 1.3472x over previous
#include <cuda_runtime.h>
#include <cuda_bf16.h>

#define MAXN 100000
#define MAXE 1600000
#define MAXF 128

// ---------------- scratch (device globals; no cudaMalloc allowed) ----------------
__device__ float g_bufA[MAXN * MAXF];
__device__ float g_bufB[MAXN * MAXF];
__device__ int   g_deg[MAXN];
__device__ float g_dinv[MAXN];
__device__ int   g_rowptr[MAXN + 1];
__device__ int   g_fill[MAXN];
__device__ int   g_esrc[MAXE];
__device__ float g_enrm[MAXE];
__device__ int   g_blocksum[64];
__device__ int   g_blockoff[64];

// ---------------- preprocessing ----------------
__global__ void zero_kernel(int N) {
    int i = blockIdx.x * blockDim.x + threadIdx.x;
    if (i < N) { g_deg[i] = 0; g_fill[i] = 0; }
}

__global__ void deg_kernel(const int* __restrict__ dst, int E) {
    int e = blockIdx.x * blockDim.x + threadIdx.x;
    if (e < E) atomicAdd(&g_deg[dst[e]], 1);
}

// ---- 3-phase exclusive scan of g_deg -> g_rowptr ----
// Phase 1: per-block (4096 elems) local exclusive scan + block sums.
__global__ void scan1_kernel(int N) {
    const int T = 1024, EL = 4;
    int t = threadIdx.x;
    int base = blockIdx.x * (T * EL) + t * EL;
    int v[EL];
    int s = 0;
#pragma unroll
    for (int j = 0; j < EL; j++) {
        int i = base + j;
        v[j] = (i < N) ? g_deg[i] : 0;
        s += v[j];
    }
    __shared__ int sh[T];
    sh[t] = s;
    __syncthreads();
    for (int o = 1; o < T; o <<= 1) {
        int u = (t >= o) ? sh[t - o] : 0;
        __syncthreads();
        sh[t] += u;
        __syncthreads();
    }
    int run = (t == 0) ? 0 : sh[t - 1];
#pragma unroll
    for (int j = 0; j < EL; j++) {
        int i = base + j;
        if (i < N) g_rowptr[i] = run;
        run += v[j];
    }
    if (t == T - 1) g_blocksum[blockIdx.x] = sh[T - 1];
}

// Phase 2: one warp scans the (<=32) block sums.
__global__ void scan2_kernel(int NB, int N) {
    int t = threadIdx.x;
    int x = (t < NB) ? g_blocksum[t] : 0;
    int v = x;
    for (int o = 1; o < 32; o <<= 1) {
        int u = __shfl_up_sync(0xFFFFFFFFu, v, o);
        if (t >= o) v += u;
    }
    if (t < NB) g_blockoff[t] = v - x;       // exclusive
    if (t == NB - 1) g_rowptr[N] = v;        // total
}

// Phase 3: add block offsets + compute dinv.
__global__ void scan3_kernel(int N) {
    int i = blockIdx.x * blockDim.x + threadIdx.x;
    if (i < N) {
        g_rowptr[i] += g_blockoff[i >> 12];
        g_dinv[i] = rsqrtf((float)g_deg[i] + 1.0f);
    }
}

__global__ void scatter_kernel(const int* __restrict__ src, const int* __restrict__ dst, int E) {
    int e = blockIdx.x * blockDim.x + threadIdx.x;
    if (e >= E) return;
    int s = src[e], d = dst[e];
    int pos = g_rowptr[d] + atomicAdd(&g_fill[d], 1);
    g_esrc[pos] = s;
    g_enrm[pos] = g_dinv[s] * g_dinv[d];
}

// ---------------- GEMM: out[n][f] = sum_k in[n][k]*W[k][f] (+b, relu opt) ----------------
template <int K, int F, int NPG, bool BIAS, bool RELU>
__global__ void gemm_kernel(const float* __restrict__ in, const float* __restrict__ W,
                            const float* __restrict__ b, float* __restrict__ out, int N) {
    constexpr int GROUPS = 128 / F;
    constexpr int NT = NPG * GROUPS;
    __shared__ float sx[NT * K];
    int base = blockIdx.x * NT;
    for (int i = threadIdx.x; i < NT * K; i += 128) {
        int r = i / K, c = i % K;
        int n = base + r;
        sx[i] = (n < N) ? in[n * K + c] : 0.0f;
    }
    __syncthreads();
    int f = threadIdx.x % F;
    int g = threadIdx.x / F;
    float acc[NPG];
#pragma unroll
    for (int j = 0; j < NPG; j++) acc[j] = 0.0f;

    if constexpr (K % 4 == 0) {
        for (int k = 0; k < K; k += 4) {
            float w0 = W[(k + 0) * F + f];
            float w1 = W[(k + 1) * F + f];
            float w2 = W[(k + 2) * F + f];
            float w3 = W[(k + 3) * F + f];
#pragma unroll
            for (int j = 0; j < NPG; j++) {
                const float4 x4 = *reinterpret_cast<const float4*>(&sx[(g * NPG + j) * K + k]);
                acc[j] = fmaf(x4.x, w0, acc[j]);
                acc[j] = fmaf(x4.y, w1, acc[j]);
                acc[j] = fmaf(x4.z, w2, acc[j]);
                acc[j] = fmaf(x4.w, w3, acc[j]);
            }
        }
    } else {
        for (int k = 0; k < K; k++) {
            float wv = W[k * F + f];
#pragma unroll
            for (int j = 0; j < NPG; j++)
                acc[j] = fmaf(sx[(g * NPG + j) * K + k], wv, acc[j]);
        }
    }
    float bv = BIAS ? b[f] : 0.0f;
#pragma unroll
    for (int j = 0; j < NPG; j++) {
        int n = base + g * NPG + j;
        if (n < N) {
            float v = acc[j] + bv;
            if (RELU) v = fmaxf(v, 0.0f);
            out[n * F + f] = v;
        }
    }
}

// ---------------- Aggregation (float4): out = A*h (+b, relu opt) via CSR ----------------
template <int F, bool BIAS, bool RELU>
__global__ void agg4_kernel(const float* __restrict__ h, float* __restrict__ out,
                            const float* __restrict__ b, int N) {
    constexpr int TPN = F / 4;            // threads per node
    constexpr int NPB = 128 / TPN;        // nodes per block
    int n = blockIdx.x * NPB + threadIdx.x / TPN;
    if (n >= N) return;
    int f4 = threadIdx.x % TPN;
    const float4* __restrict__ h4 = (const float4*)h;
    float di = g_dinv[n];
    float s0 = di * di;
    float4 v = h4[n * TPN + f4];
    float4 acc0 = make_float4(v.x * s0, v.y * s0, v.z * s0, v.w * s0);
    float4 acc1 = make_float4(0.f, 0.f, 0.f, 0.f);
    int beg = g_rowptr[n], end = g_rowptr[n + 1];
    int j = beg;
    for (; j + 1 < end; j += 2) {
        int sA = g_esrc[j];
        int sB = g_esrc[j + 1];
        float nA = g_enrm[j];
        float nB = g_enrm[j + 1];
        float4 a = h4[sA * TPN + f4];
        float4 c = h4[sB * TPN + f4];
        acc0.x = fmaf(a.x, nA, acc0.x);
        acc0.y = fmaf(a.y, nA, acc0.y);
        acc0.z = fmaf(a.z, nA, acc0.z);
        acc0.w = fmaf(a.w, nA, acc0.w);
        acc1.x = fmaf(c.x, nB, acc1.x);
        acc1.y = fmaf(c.y, nB, acc1.y);
        acc1.z = fmaf(c.z, nB, acc1.z);
        acc1.w = fmaf(c.w, nB, acc1.w);
    }
    if (j < end) {
        int sA = g_esrc[j];
        float nA = g_enrm[j];
        float4 a = h4[sA * TPN + f4];
        acc0.x = fmaf(a.x, nA, acc0.x);
        acc0.y = fmaf(a.y, nA, acc0.y);
        acc0.z = fmaf(a.z, nA, acc0.z);
        acc0.w = fmaf(a.w, nA, acc0.w);
    }
    float4 r = make_float4(acc0.x + acc1.x, acc0.y + acc1.y,
                           acc0.z + acc1.z, acc0.w + acc1.w);
    if (BIAS) {
        const float4 bv = *reinterpret_cast<const float4*>(b + f4 * 4);
        r.x += bv.x; r.y += bv.y; r.z += bv.z; r.w += bv.w;
    }
    if (RELU) {
        r.x = fmaxf(r.x, 0.f); r.y = fmaxf(r.y, 0.f);
        r.z = fmaxf(r.z, 0.f); r.w = fmaxf(r.w, 0.f);
    }
    ((float4*)out)[n * TPN + f4] = r;
}

// scalar aggregation for F=2 (layer-1 input)
__global__ void agg2_kernel(const float* __restrict__ h, float* __restrict__ out, int N) {
    int n = blockIdx.x * 64 + threadIdx.x / 2;
    if (n >= N) return;
    int f = threadIdx.x % 2;
    float di = g_dinv[n];
    float acc = h[n * 2 + f] * di * di;
    int beg = g_rowptr[n], end = g_rowptr[n + 1];
    for (int j = beg; j < end; j++)
        acc = fmaf(h[g_esrc[j] * 2 + f], g_enrm[j], acc);
    out[n * 2 + f] = acc;
}

// ---------------- final linear: out[n] = x[n,0:64] . Wl + bl ----------------
__global__ void linear_kernel(const float* __restrict__ x, const float* __restrict__ Wl,
                              const float* __restrict__ bl, float* __restrict__ out, int N) {
    int warp = (blockIdx.x * blockDim.x + threadIdx.x) >> 5;
    int lane = threadIdx.x & 31;
    if (warp >= N) return;
    float v = x[warp * 64 + lane] * Wl[lane] + x[warp * 64 + 32 + lane] * Wl[32 + lane];
#pragma unroll
    for (int o = 16; o; o >>= 1) v += __shfl_xor_sync(0xFFFFFFFFu, v, o);
    if (lane == 0) out[warp] = v + bl[0];
}

// ---------------- launch ----------------
extern "C" void kernel_launch(void* const* d_in, const int* in_sizes, int n_in,
                              void* d_out, int out_size) {
    const float* x  = (const float*)d_in[0];
    const int*   ei = (const int*)d_in[1];
    int wb = n_in - 12;
    const float* W1 = (const float*)d_in[wb + 0];
    const float* b1 = (const float*)d_in[wb + 1];
    const float* W2 = (const float*)d_in[wb + 2];
    const float* b2 = (const float*)d_in[wb + 3];
    const float* W3 = (const float*)d_in[wb + 4];
    const float* b3 = (const float*)d_in[wb + 5];
    const float* W4 = (const float*)d_in[wb + 6];
    const float* b4 = (const float*)d_in[wb + 7];
    const float* W5 = (const float*)d_in[wb + 8];
    const float* b5 = (const float*)d_in[wb + 9];
    const float* Wl = (const float*)d_in[wb + 10];
    const float* bl = (const float*)d_in[wb + 11];
    float* out = (float*)d_out;

    int N = in_sizes[0] / 2;
    int E = in_sizes[1] / 2;
    const int* src = ei;
    const int* dst = ei + E;

    float *bufA, *bufB;
    cudaGetSymbolAddress((void**)&bufA, g_bufA);
    cudaGetSymbolAddress((void**)&bufB, g_bufB);

    // ---- build normalized CSR (dst-sorted edges) ----
    zero_kernel<<<(N + 255) / 256, 256>>>(N);
    deg_kernel<<<(E + 255) / 256, 256>>>(dst, E);
    int NB = (N + 4095) / 4096;          // <= 32 for N <= 131072
    scan1_kernel<<<NB, 1024>>>(N);
    scan2_kernel<<<1, 32>>>(NB, N);
    scan3_kernel<<<(N + 1023) / 1024, 1024>>>(N);
    scatter_kernel<<<(E + 255) / 256, 256>>>(src, dst, E);

    // ---- layer 1: t = A x (F=2) ; x1 = relu(t W1 + b1) ----
    agg2_kernel<<<(N + 63) / 64, 128>>>(x, bufB, N);
    gemm_kernel<2, 128, 8, true, true><<<(N + 7) / 8, 128>>>(bufB, W1, b1, bufA, N);

    // ---- layer 2: t = A x1 (F=128) ; x2 = relu(t W2 + b2) ----
    agg4_kernel<128, false, false><<<(N + 3) / 4, 128>>>(bufA, bufB, nullptr, N);
    gemm_kernel<128, 128, 16, true, true><<<(N + 15) / 16, 128>>>(bufB, W2, b2, bufA, N);

    // ---- layer 3: t = x2 W3 (no bias) ; x3 = relu(A t + b3) (F=32) ----
    gemm_kernel<128, 32, 8, false, false><<<(N + 31) / 32, 128>>>(bufA, W3, nullptr, bufB, N);
    agg4_kernel<32, true, true><<<(N + 15) / 16, 128>>>(bufB, bufA, b3, N);

    // ---- layer 4: t = A x3 (F=32) ; x4 = relu(t W4 + b4) ----
    agg4_kernel<32, false, false><<<(N + 15) / 16, 128>>>(bufA, bufB, nullptr, N);
    gemm_kernel<32, 32, 8, true, true><<<(N + 31) / 32, 128>>>(bufB, W4, b4, bufA, N);

    // ---- layer 5: t = A x4 (F=32) ; x5 = relu(t W5 + b5) (F=64) ----
    agg4_kernel<32, false, false><<<(N + 15) / 16, 128>>>(bufA, bufB, nullptr, N);
    gemm_kernel<32, 64, 8, true, true><<<(N + 15) / 16, 128>>>(bufB, W5, b5, bufA, N);

    // ---- final linear 64 -> 1 ----
    linear_kernel<<<(N * 32 + 255) / 256, 256>>>(bufA, Wl, bl, out, N);
}